// round 3
// baseline (speedup 1.0000x reference)
#include <cuda_runtime.h>
#include <math.h>

#define U_DIM   100000
#define B_DIM   128
#define NN_DIM  100
#define K_DIM   500
#define NRUNS   10
#define NPAIRS  124750.0   // 500*499/2

// ---------------- device scratch (no allocations allowed) ----------------
__device__ int    g_choice[NRUNS];
__device__ double g_sums[NRUNS][5];                  // sr, sd, srr, sdd, srd
__device__ float  g_xhat[NRUNS * K_DIM * B_DIM];     // unit-norm centered feature vectors
__device__ float  g_px[NRUNS * 512];
__device__ float  g_py[NRUNS * 512];

// ---------------- kernel 1: threefry2x32 -> choice; zero sums ----------------
__global__ void k_init() {
    int t = threadIdx.x;
    if (t == 0) {
        // jax.random.key(42) -> key data (0, 42)
        unsigned ks[3];
        ks[0] = 0u;
        ks[1] = 42u;
        ks[2] = 0u ^ 42u ^ 0x1BD11BDAu;
        const int rot[2][4] = {{13, 15, 26, 6}, {17, 29, 16, 24}};
        // counts = iota(10); lanes: x0 = counts[0:5], x1 = counts[5:10]
        for (int p = 0; p < 5; p++) {
            unsigned x0 = (unsigned)p + ks[0];
            unsigned x1 = (unsigned)(p + 5) + ks[1];
            for (int g = 0; g < 5; g++) {
                #pragma unroll
                for (int q = 0; q < 4; q++) {
                    int rr = rot[g & 1][q];
                    x0 += x1;
                    x1 = (x1 << rr) | (x1 >> (32 - rr));
                    x1 ^= x0;
                }
                x0 += ks[(g + 1) % 3];
                x1 += ks[(g + 2) % 3] + (unsigned)(g + 1);
            }
            // jax _randint (nbits=32): hi/lo halves of ONE 32-bit draw.
            // multiplier = (2^16 % 100)^2 % 100 = 96
            // offset = ((bits>>16)%100 * 96 + (bits&0xFFFF)%100) % 100
            unsigned b0 = x0, b1 = x1;
            g_choice[p]     = (int)((((b0 >> 16) % 100u) * 96u + (b0 & 0xFFFFu) % 100u) % 100u);
            g_choice[p + 5] = (int)((((b1 >> 16) % 100u) * 96u + (b1 & 0xFFFFu) % 100u) % 100u);
        }
    }
    if (t < NRUNS * 5) ((double*)g_sums)[t] = 0.0;
}

// ---------------- kernel 2: gather columns, center, normalize ----------------
// grid (K_DIM, NRUNS), 128 threads (one per feature row b)
__global__ void k_gather(const float* __restrict__ feat,
                         const float* __restrict__ pos,
                         const int*   __restrict__ neigh) {
    int r = blockIdx.y;
    int k = blockIdx.x;
    int b = threadIdx.x;

    int c   = g_choice[r];
    int ind = neigh[c * K_DIM + k];

    float v = feat[b * U_DIM + ind];

    __shared__ float sbuf[4];
    // mean over B
    float s = v;
    #pragma unroll
    for (int o = 16; o > 0; o >>= 1) s += __shfl_down_sync(0xFFFFFFFFu, s, o);
    if ((b & 31) == 0) sbuf[b >> 5] = s;
    __syncthreads();
    float mean = (sbuf[0] + sbuf[1] + sbuf[2] + sbuf[3]) * (1.0f / 128.0f);
    __syncthreads();

    float xc = v - mean;
    float q  = xc * xc;
    #pragma unroll
    for (int o = 16; o > 0; o >>= 1) q += __shfl_down_sync(0xFFFFFFFFu, q, o);
    if ((b & 31) == 0) sbuf[b >> 5] = q;
    __syncthreads();
    float n2 = sbuf[0] + sbuf[1] + sbuf[2] + sbuf[3];

    float scale = rsqrtf(n2);
    g_xhat[(r * K_DIM + k) * B_DIM + b] = xc * scale;

    if (b == 0) {
        g_px[r * 512 + k] = pos[ind * 2 + 0];
        g_py[r * 512 + k] = pos[ind * 2 + 1];
    }
}

// ---------------- kernel 3: tiled pair reduction ----------------
// grid (36 lower-tri tile pairs, NRUNS), 256 threads
// tile 64x64 nodes, K chunked by 32, 4x4 register micro-tiles
__global__ __launch_bounds__(256) void k_pairs() {
    int r = blockIdx.y;
    int t = blockIdx.x;            // 0..35
    int ti = 0;
    while ((ti + 1) * (ti + 2) / 2 <= t) ti++;
    int tj = t - ti * (ti + 1) / 2;

    __shared__ __align__(16) float As[32][64];
    __shared__ __align__(16) float Bs[32][64];
    __shared__ float pax[64], pay[64], pbx[64], pby[64];
    __shared__ double redbuf[8][5];

    int tid = threadIdx.x;
    int tx = tid & 15;
    int ty = tid >> 4;

    // positions into smem
    if (tid < 64) {
        int i = ti * 64 + tid;
        pax[tid] = (i < K_DIM) ? g_px[r * 512 + i] : 0.0f;
        pay[tid] = (i < K_DIM) ? g_py[r * 512 + i] : 0.0f;
    } else if (tid < 128) {
        int n = tid - 64;
        int j = tj * 64 + n;
        pbx[n] = (j < K_DIM) ? g_px[r * 512 + j] : 0.0f;
        pby[n] = (j < K_DIM) ? g_py[r * 512 + j] : 0.0f;
    }

    // load-phase mapping: each thread owns (node = tid>>2, 8 consecutive k's)
    int nloc  = tid >> 2;
    int kg    = (tid & 3) * 8;
    int nodeA = ti * 64 + nloc;
    int nodeB = tj * 64 + nloc;
    const float* baseA = (nodeA < K_DIM) ? &g_xhat[(r * K_DIM + nodeA) * B_DIM] : 0;
    const float* baseB = (nodeB < K_DIM) ? &g_xhat[(r * K_DIM + nodeB) * B_DIM] : 0;

    float acc[4][4];
    #pragma unroll
    for (int u = 0; u < 4; u++)
        #pragma unroll
        for (int v = 0; v < 4; v++) acc[u][v] = 0.0f;

    for (int chunk = 0; chunk < 4; chunk++) {
        __syncthreads();
        int k0 = chunk * 32 + kg;
        float4 a0 = make_float4(0.f, 0.f, 0.f, 0.f), a1 = a0, b0 = a0, b1 = a0;
        if (baseA) { a0 = *(const float4*)(baseA + k0); a1 = *(const float4*)(baseA + k0 + 4); }
        if (baseB) { b0 = *(const float4*)(baseB + k0); b1 = *(const float4*)(baseB + k0 + 4); }
        As[kg + 0][nloc] = a0.x; As[kg + 1][nloc] = a0.y; As[kg + 2][nloc] = a0.z; As[kg + 3][nloc] = a0.w;
        As[kg + 4][nloc] = a1.x; As[kg + 5][nloc] = a1.y; As[kg + 6][nloc] = a1.z; As[kg + 7][nloc] = a1.w;
        Bs[kg + 0][nloc] = b0.x; Bs[kg + 1][nloc] = b0.y; Bs[kg + 2][nloc] = b0.z; Bs[kg + 3][nloc] = b0.w;
        Bs[kg + 4][nloc] = b1.x; Bs[kg + 5][nloc] = b1.y; Bs[kg + 6][nloc] = b1.z; Bs[kg + 7][nloc] = b1.w;
        __syncthreads();

        #pragma unroll 8
        for (int kk = 0; kk < 32; kk++) {
            float4 a4 = *(const float4*)&As[kk][ty * 4];
            float4 b4 = *(const float4*)&Bs[kk][tx * 4];
            float av[4] = {a4.x, a4.y, a4.z, a4.w};
            float bv[4] = {b4.x, b4.y, b4.z, b4.w};
            #pragma unroll
            for (int u = 0; u < 4; u++)
                #pragma unroll
                for (int v = 0; v < 4; v++)
                    acc[u][v] = fmaf(av[u], bv[v], acc[u][v]);
        }
    }

    // per-thread pair stats in fp64
    double sr = 0.0, sd = 0.0, srr = 0.0, sdd = 0.0, srd = 0.0;
    #pragma unroll
    for (int u = 0; u < 4; u++) {
        int i = ti * 64 + ty * 4 + u;
        #pragma unroll
        for (int v = 0; v < 4; v++) {
            int j = tj * 64 + tx * 4 + v;
            if (i < K_DIM && j < K_DIM && i > j) {
                float cr = acc[u][v];
                float dx = pax[ty * 4 + u] - pbx[tx * 4 + v];
                float dy = pay[ty * 4 + u] - pby[tx * 4 + v];
                float ds = 1.0f / (sqrtf(dx * dx + dy * dy) + 1.0f);
                sr  += (double)cr;
                sd  += (double)ds;
                srr += (double)cr * cr;
                sdd += (double)ds * ds;
                srd += (double)cr * ds;
            }
        }
    }

    // warp reduce 5 doubles
    #pragma unroll
    for (int o = 16; o > 0; o >>= 1) {
        sr  += __shfl_down_sync(0xFFFFFFFFu, sr,  o);
        sd  += __shfl_down_sync(0xFFFFFFFFu, sd,  o);
        srr += __shfl_down_sync(0xFFFFFFFFu, srr, o);
        sdd += __shfl_down_sync(0xFFFFFFFFu, sdd, o);
        srd += __shfl_down_sync(0xFFFFFFFFu, srd, o);
    }
    int wid = tid >> 5;
    if ((tid & 31) == 0) {
        redbuf[wid][0] = sr;  redbuf[wid][1] = sd;  redbuf[wid][2] = srr;
        redbuf[wid][3] = sdd; redbuf[wid][4] = srd;
    }
    __syncthreads();
    if (tid < 5) {
        double acc5 = 0.0;
        #pragma unroll
        for (int w = 0; w < 8; w++) acc5 += redbuf[w][tid];
        atomicAdd(&g_sums[r][tid], acc5);
    }
}

// ---------------- kernel 4: Pearson per run, mean loss ----------------
__global__ void k_final(float* __restrict__ out) {
    int i = threadIdx.x;
    double loss = 0.0;
    if (i < NRUNS) {
        double sr  = g_sums[i][0];
        double sd  = g_sums[i][1];
        double srr = g_sums[i][2];
        double sdd = g_sums[i][3];
        double srd = g_sums[i][4];
        double P = NPAIRS;
        double ca  = srr - sr * sr / P;
        double cb  = sdd - sd * sd / P;
        double cab = srd - sr * sd / P;
        double rr  = cab / sqrt(ca * cb);
        loss = (1.0 - rr) * 0.5;
    }
    #pragma unroll
    for (int o = 16; o > 0; o >>= 1) loss += __shfl_down_sync(0xFFFFFFFFu, loss, o);
    if (i == 0) out[0] = (float)(loss / (double)NRUNS);
}

// ---------------- launch ----------------
extern "C" void kernel_launch(void* const* d_in, const int* in_sizes, int n_in,
                              void* d_out, int out_size) {
    const float* feat  = (const float*)d_in[0];   // [128, 100000]
    const float* pos   = (const float*)d_in[1];   // [100000, 2]
    const int*   neigh = (const int*)  d_in[2];   // [100, 500]
    float* out = (float*)d_out;

    k_init<<<1, 64>>>();
    k_gather<<<dim3(K_DIM, NRUNS), B_DIM>>>(feat, pos, neigh);
    k_pairs<<<dim3(36, NRUNS), 256>>>();
    k_final<<<1, 32>>>(out);
}